// round 1
// baseline (speedup 1.0000x reference)
#include <cuda_runtime.h>
#include <math.h>

#define SRC_LEN 48
#define TGT_LEN 48
#define BATCH   64
#define HID     512
#define G4      2048        // 4*HID
#define VOCAB   32000
#define DSTEPS  47          // TGT_LEN-1
#define NROWS   3008        // DSTEPS*BATCH
#define NROWS_PAD 3072

// ---------------- scratch (device globals; zero-initialized at load) --------
__device__ float g_Ge[SRC_LEN * BATCH * G4];    // encoder input-side gates
__device__ float g_Gd[DSTEPS  * BATCH * G4];    // decoder input-side gates
__device__ float g_H[2][BATCH * HID];           // ping-pong hidden
__device__ float g_C[2][BATCH * HID];           // ping-pong cell
__device__ float g_Hall[NROWS_PAD * HID];       // decoder h2 per step (padded rows stay 0)
__device__ float g_rowsum[NROWS];               // sum(exp(logits)) per row
__device__ float g_rowtgt[NROWS];               // logit at target per row

__device__ __forceinline__ float sigmoidf_(float x) {
    return 1.0f / (1.0f + __expf(-x));
}

// ---------------- init: zero h0, c0, rowsum ---------------------------------
__global__ void init_kernel() {
    int i = blockIdx.x * blockDim.x + threadIdx.x;
    if (i < BATCH * HID) { g_H[0][i] = 0.0f; g_C[0][i] = 0.0f; }
    if (i < NROWS) g_rowsum[i] = 0.0f;
}

// ---------------- batched embed + input-gate GEMM ---------------------------
// G[r][n] = emb_z[tok[r]] . W[n] + b1[n] + b2[n], r = t*BATCH+b
// Tile 64x64, BK=32, 256 threads, 4x4 microtile.
__global__ __launch_bounds__(256) void embed_gemm_kernel(
    const int*   __restrict__ toks,   // [R]
    const float* __restrict__ emb,    // [V][HID]
    const float* __restrict__ W,      // [G4][HID]
    const float* __restrict__ b1,
    const float* __restrict__ b2,
    int is_enc)
{
    __shared__ float As[32][68];   // [k][m], pitch 68 -> rows 16B aligned
    __shared__ float Bs[32][68];   // [k][n]
    float* __restrict__ G = is_enc ? g_Ge : g_Gd;

    int m0 = blockIdx.y * 64;
    int n0 = blockIdx.x * 64;
    int tid = threadIdx.x;
    int tx = tid & 15;             // n quad
    int ty = tid >> 4;             // m quad
    float acc[4][4] = {};

    for (int k0 = 0; k0 < HID; k0 += 32) {
        #pragma unroll
        for (int l = 0; l < 2; l++) {
            int idx = tid + l * 256;            // 0..511
            int m   = idx >> 3;                 // 0..63
            int kq  = idx & 7;                  // float4 slot (8 per row)
            int tok = toks[m0 + m];
            float4 a = make_float4(0.f, 0.f, 0.f, 0.f);
            if (tok != 0) a = *(const float4*)&emb[tok * HID + k0 + kq * 4];
            As[kq*4+0][m] = a.x; As[kq*4+1][m] = a.y;
            As[kq*4+2][m] = a.z; As[kq*4+3][m] = a.w;
            float4 w = *(const float4*)&W[(n0 + m) * HID + k0 + kq * 4];
            Bs[kq*4+0][m] = w.x; Bs[kq*4+1][m] = w.y;
            Bs[kq*4+2][m] = w.z; Bs[kq*4+3][m] = w.w;
        }
        __syncthreads();
        #pragma unroll
        for (int k = 0; k < 32; k++) {
            float4 a = *(const float4*)&As[k][ty * 4];
            float4 b = *(const float4*)&Bs[k][tx * 4];
            float ar[4] = {a.x, a.y, a.z, a.w};
            float br[4] = {b.x, b.y, b.z, b.w};
            #pragma unroll
            for (int i = 0; i < 4; i++)
                #pragma unroll
                for (int j = 0; j < 4; j++)
                    acc[i][j] = fmaf(ar[i], br[j], acc[i][j]);
        }
        __syncthreads();
    }
    #pragma unroll
    for (int i = 0; i < 4; i++) {
        int gm = m0 + ty * 4 + i;
        float4 o;
        int gn = n0 + tx * 4;
        o.x = acc[i][0] + b1[gn+0] + b2[gn+0];
        o.y = acc[i][1] + b1[gn+1] + b2[gn+1];
        o.z = acc[i][2] + b1[gn+2] + b2[gn+2];
        o.w = acc[i][3] + b1[gn+3] + b2[gn+3];
        *(float4*)&G[gm * G4 + gn] = o;
    }
}

// ---------------- one LSTM step: gates += h @ W_hh^T, then cell update ------
// Block owns 8 hidden units (x4 gates = 32 gate rows, strided groups) x 32 batch.
// Grid (64, 2), 128 threads. Fused update thanks to gate-aligned row tiling.
__global__ __launch_bounds__(128) void lstm_step_kernel(
    const float* __restrict__ Whh,         // [G4][HID]
    const int*   __restrict__ toks,        // input_lines (enc mask) base
    int is_enc, int t, int pin, int pout)
{
    __shared__ float As[32][34];   // [k][b]  (8B-aligned rows for float2)
    __shared__ float Bs[32][36];   // [k][r]  (16B-aligned rows for float4)
    __shared__ float gt[32][33];   // gates [r][b]

    const float* __restrict__ G   = (is_enc ? g_Ge : g_Gd) + t * BATCH * G4;
    const float* __restrict__ h_in = g_H[pin];
    const float* __restrict__ c_in = g_C[pin];
    float* __restrict__ h_out = g_H[pout];
    float* __restrict__ c_out = g_C[pout];

    int j0 = blockIdx.x * 8;       // hidden unit base
    int b0 = blockIdx.y * 32;      // batch base
    int tid = threadIdx.x;
    int tx = tid & 15;             // batch pair (2 batches)
    int ty = tid >> 4;             // row quad (4 gate rows)
    float acc[2][4] = {};

    for (int k0 = 0; k0 < HID; k0 += 32) {
        #pragma unroll
        for (int l = 0; l < 2; l++) {
            int idx = tid + l * 128;            // 0..255
            int r   = idx >> 3;                 // 0..31
            int kq  = idx & 7;
            float4 a = *(const float4*)&h_in[(b0 + r) * HID + k0 + kq * 4];
            As[kq*4+0][r] = a.x; As[kq*4+1][r] = a.y;
            As[kq*4+2][r] = a.z; As[kq*4+3][r] = a.w;
            int grow = (r >> 3) * HID + j0 + (r & 7);   // gate-group * 512 + j
            float4 w = *(const float4*)&Whh[grow * HID + k0 + kq * 4];
            Bs[kq*4+0][r] = w.x; Bs[kq*4+1][r] = w.y;
            Bs[kq*4+2][r] = w.z; Bs[kq*4+3][r] = w.w;
        }
        __syncthreads();
        #pragma unroll
        for (int k = 0; k < 32; k++) {
            float2 a = *(const float2*)&As[k][tx * 2];
            float4 w = *(const float4*)&Bs[k][ty * 4];
            acc[0][0] = fmaf(a.x, w.x, acc[0][0]);
            acc[0][1] = fmaf(a.x, w.y, acc[0][1]);
            acc[0][2] = fmaf(a.x, w.z, acc[0][2]);
            acc[0][3] = fmaf(a.x, w.w, acc[0][3]);
            acc[1][0] = fmaf(a.y, w.x, acc[1][0]);
            acc[1][1] = fmaf(a.y, w.y, acc[1][1]);
            acc[1][2] = fmaf(a.y, w.z, acc[1][2]);
            acc[1][3] = fmaf(a.y, w.w, acc[1][3]);
        }
        __syncthreads();
    }

    // stage gates (+ precomputed input-side part) to smem
    #pragma unroll
    for (int i = 0; i < 2; i++) {
        int b = b0 + tx * 2 + i;
        #pragma unroll
        for (int q = 0; q < 4; q++) {
            int r = ty * 4 + q;
            int gcol = (r >> 3) * HID + j0 + (r & 7);
            gt[r][tx * 2 + i] = acc[i][q] + G[b * G4 + gcol];
        }
    }
    __syncthreads();

    // cell update: 8 j x 32 b = 256 elems / 128 threads
    #pragma unroll
    for (int l = 0; l < 2; l++) {
        int idx = tid + l * 128;
        int jj = idx >> 5;         // 0..7
        int bb = idx & 31;
        int b = b0 + bb;
        int j = j0 + jj;
        float iv = gt[      jj][bb];
        float fv = gt[ 8 +  jj][bb];
        float gv = gt[16 +  jj][bb];
        float ov = gt[24 +  jj][bb];
        float c  = c_in[b * HID + j];
        float h  = h_in[b * HID + j];
        float c2 = sigmoidf_(fv) * c + sigmoidf_(iv) * tanhf(gv);
        float h2 = sigmoidf_(ov) * tanhf(c2);
        if (is_enc && toks[t * BATCH + b] == 0) { c2 = c; h2 = h; }
        c_out[b * HID + j] = c2;
        h_out[b * HID + j] = h2;
        if (!is_enc) g_Hall[(t * BATCH + b) * HID + j] = h2;
    }
}

// ---------------- batched projection + fused log-softmax loss pieces --------
// C = Hall @ W_out^T (+ b_out); never materialized: per row accumulate
// sum(exp(logit)) via atomics and capture logit at target column.
// Tile 128x128, BK=16, 256 threads, 8x8 microtile.
__global__ __launch_bounds__(256) void proj_loss_kernel(
    const float* __restrict__ W,        // W_out [VOCAB][HID]
    const float* __restrict__ bout,     // [VOCAB]
    const int*   __restrict__ targets)  // target_lines flat [48*64]
{
    __shared__ float As[16][132];
    __shared__ float Bs[16][132];
    const float* __restrict__ A = g_Hall;

    int m0 = blockIdx.y * 128;
    int n0 = blockIdx.x * 128;
    int tid = threadIdx.x;
    int tx = tid & 15;
    int ty = tid >> 4;
    float acc[8][8] = {};

    for (int k0 = 0; k0 < HID; k0 += 16) {
        #pragma unroll
        for (int l = 0; l < 2; l++) {
            int idx = tid + l * 256;            // 0..511
            int m   = idx >> 2;                 // 0..127
            int kq  = idx & 3;                  // 4 float4 slots = 16 k
            float4 a = *(const float4*)&A[(m0 + m) * HID + k0 + kq * 4];
            As[kq*4+0][m] = a.x; As[kq*4+1][m] = a.y;
            As[kq*4+2][m] = a.z; As[kq*4+3][m] = a.w;
            float4 w = *(const float4*)&W[(n0 + m) * HID + k0 + kq * 4];
            Bs[kq*4+0][m] = w.x; Bs[kq*4+1][m] = w.y;
            Bs[kq*4+2][m] = w.z; Bs[kq*4+3][m] = w.w;
        }
        __syncthreads();
        #pragma unroll
        for (int k = 0; k < 16; k++) {
            float4 a0 = *(const float4*)&As[k][ty * 4];
            float4 a1 = *(const float4*)&As[k][64 + ty * 4];
            float4 w0 = *(const float4*)&Bs[k][tx * 4];
            float4 w1 = *(const float4*)&Bs[k][64 + tx * 4];
            float ar[8] = {a0.x, a0.y, a0.z, a0.w, a1.x, a1.y, a1.z, a1.w};
            float wr[8] = {w0.x, w0.y, w0.z, w0.w, w1.x, w1.y, w1.z, w1.w};
            #pragma unroll
            for (int i = 0; i < 8; i++)
                #pragma unroll
                for (int j = 0; j < 8; j++)
                    acc[i][j] = fmaf(ar[i], wr[j], acc[i][j]);
        }
        __syncthreads();
    }

    // epilogue: bias add, exp-sum per row (reduced over the 16 tx lanes),
    // target-logit capture. Padded rows (gm >= NROWS) are zero-A -> finite,
    // and excluded from accumulation.
    int   gncol[8];
    float bj[8];
    #pragma unroll
    for (int j = 0; j < 8; j++) {
        gncol[j] = n0 + (j < 4 ? tx * 4 + j : 64 + tx * 4 + (j - 4));
        bj[j] = bout[gncol[j]];
    }
    #pragma unroll
    for (int i = 0; i < 8; i++) {
        int gm = m0 + (i < 4 ? ty * 4 + i : 64 + ty * 4 + (i - 4));
        bool valid = (gm < NROWS);
        int tgt = valid ? targets[gm + BATCH] : -1;   // tgt_next = row shifted by one step
        float s = 0.0f;
        #pragma unroll
        for (int j = 0; j < 8; j++) {
            float logit = acc[i][j] + bj[j];
            s += __expf(logit);
            if (valid && gncol[j] == tgt) g_rowtgt[gm] = logit;
        }
        // reduce across the 16 threads sharing this row (width-16 xor shuffle)
        #pragma unroll
        for (int o = 8; o > 0; o >>= 1)
            s += __shfl_xor_sync(0xffffffffu, s, o, 16);
        if (valid && tx == 0) atomicAdd(&g_rowsum[gm], s);
    }
}

// ---------------- final loss reduction --------------------------------------
__global__ void loss_reduce_kernel(float* __restrict__ out)
{
    __shared__ float sbuf[256];
    int tid = threadIdx.x;
    float s = 0.0f;
    for (int r = tid; r < NROWS; r += 256)
        s += logf(g_rowsum[r]) - g_rowtgt[r];
    sbuf[tid] = s;
    __syncthreads();
    for (int o = 128; o > 0; o >>= 1) {
        if (tid < o) sbuf[tid] += sbuf[tid + o];
        __syncthreads();
    }
    if (tid == 0) out[0] = sbuf[0] / (float)BATCH;
}

// ---------------- launch ----------------------------------------------------
extern "C" void kernel_launch(void* const* d_in, const int* in_sizes, int n_in,
                              void* d_out, int out_size)
{
    (void)in_sizes; (void)n_in; (void)out_size;
    const int*   input_lines  = (const int*)  d_in[0];
    const int*   target_lines = (const int*)  d_in[1];
    const float* emb_in       = (const float*)d_in[2];
    const float* emb_tgt      = (const float*)d_in[3];
    const float* W_ih_e       = (const float*)d_in[4];
    const float* W_hh_e       = (const float*)d_in[5];
    const float* b_ih_e       = (const float*)d_in[6];
    const float* b_hh_e       = (const float*)d_in[7];
    const float* W_ih_d       = (const float*)d_in[8];
    const float* W_hh_d       = (const float*)d_in[9];
    const float* b_ih_d       = (const float*)d_in[10];
    const float* b_hh_d       = (const float*)d_in[11];
    const float* W_out        = (const float*)d_in[12];
    const float* b_out        = (const float*)d_in[13];
    float* out = (float*)d_out;

    // 1) zero h0/c0/rowsum
    init_kernel<<<(BATCH * HID + 255) / 256, 256>>>();

    // 2) batched input-side gate GEMMs (token-dependent only, no recurrence)
    embed_gemm_kernel<<<dim3(G4 / 64, SRC_LEN), 256>>>(
        input_lines, emb_in, W_ih_e, b_ih_e, b_hh_e, 1);
    embed_gemm_kernel<<<dim3(G4 / 64, DSTEPS), 256>>>(
        target_lines, emb_tgt, W_ih_d, b_ih_d, b_hh_d, 0);

    // 3) encoder recurrence (48 steps)
    for (int t = 0; t < SRC_LEN; t++)
        lstm_step_kernel<<<dim3(HID / 8, 2), 128>>>(
            W_hh_e, input_lines, 1, t, t & 1, (t + 1) & 1);

    // 4) decoder recurrence (47 steps); parity continues (enc ends at 0)
    for (int t = 0; t < DSTEPS; t++)
        lstm_step_kernel<<<dim3(HID / 8, 2), 128>>>(
            W_hh_d, input_lines, 0, t, t & 1, (t + 1) & 1);

    // 5) batched output projection + fused loss pieces
    proj_loss_kernel<<<dim3(VOCAB / 128, NROWS_PAD / 128), 256>>>(
        W_out, b_out, target_lines);

    // 6) final scalar loss
    loss_reduce_kernel<<<1, 256>>>(out);
}

// round 8
// speedup vs baseline: 1.2418x; 1.2418x over previous
#include <cuda_runtime.h>
#include <math.h>

#define SRC_LEN 48
#define TGT_LEN 48
#define BATCH   64
#define HID     512
#define G4      2048
#define VOCAB   32000
#define DSTEPS  47
#define NROWS   3008
#define NROWS_PAD 3072
#define WPITCH  24           // Wsm pitch: banks distinct per 8-lane phase
#define HPITCH  68           // hs/gsm pitch

// ---------------- scratch (device globals; zero at module load) -------------
// NOTE: these symbols are referenced ONLY from device code. Passing them as
// kernel arguments from host code is UB (host shadow address) and was the
// cause of the 128 MiB device-memory rule violations in rounds 2/4/6.
__device__ float g_Ge[SRC_LEN * 4 * HID * BATCH];   // [t][g][j][b]
__device__ float g_Gd[DSTEPS  * 4 * HID * BATCH];   // [t][g][j][b]
__device__ float g_Hpp[2][HID * BATCH];             // h' [j][b], ping-pong
__device__ float g_Cst[HID * BATCH];                // c  [j][b], in-place
__device__ float g_Hall[HID * NROWS_PAD];           // Hall' [j][m]; pad cols stay 0
__device__ float g_rowsum[NROWS];
__device__ float g_rowtgt[NROWS];

__device__ __forceinline__ float sigmoidf_(float x) {
    return 1.0f / (1.0f + __expf(-x));
}

__device__ __forceinline__ unsigned smem_u32(const void* p) {
    return (unsigned)__cvta_generic_to_shared(p);
}
__device__ __forceinline__ void cp_async16(unsigned s, const void* g) {
    asm volatile("cp.async.cg.shared.global [%0], [%1], 16;" :: "r"(s), "l"(g));
}

// ---------------- init: zero h0, c, rowsum -----------------------------------
__global__ void init_kernel() {
    int i = blockIdx.x * blockDim.x + threadIdx.x;
    if (i < HID * BATCH) { g_Hpp[0][i] = 0.0f; g_Cst[i] = 0.0f; }
    if (i < NROWS) g_rowsum[i] = 0.0f;
}

// ---------------- embed + input-gate GEMM, 128x128 tile, 8x8 microtile ------
// C[m][n] = emb_z[tok[m]] . W[n] + b1[n] + b2[n], written transposed into
// Gout[t][g][j][b] with m = t*64+b, n = g*512+j. Gout selected IN DEVICE CODE.
__global__ __launch_bounds__(256) void embed_gemm128(
    const int*   __restrict__ toks,
    const float* __restrict__ emb,
    const float* __restrict__ W,
    const float* __restrict__ b1,
    const float* __restrict__ b2,
    int is_enc,
    int R)
{
    __shared__ float As[16][132];
    __shared__ float Bs[16][132];
    float* __restrict__ Gout = is_enc ? g_Ge : g_Gd;   // device-side resolve

    int m0 = blockIdx.y * 128;
    int n0 = blockIdx.x * 128;
    int tid = threadIdx.x;
    int tx = tid & 15;
    int ty = tid >> 4;
    float acc[8][8] = {};

    for (int k0 = 0; k0 < HID; k0 += 16) {
        #pragma unroll
        for (int l = 0; l < 2; l++) {
            int idx = tid + l * 256;
            int m   = idx >> 2;
            int kq  = idx & 3;
            int gm  = m0 + m;
            int tok = (gm < R) ? toks[gm] : 0;
            float4 a = make_float4(0.f, 0.f, 0.f, 0.f);
            if (tok != 0) a = *(const float4*)&emb[(size_t)tok * HID + k0 + kq * 4];
            As[kq*4+0][m] = a.x; As[kq*4+1][m] = a.y;
            As[kq*4+2][m] = a.z; As[kq*4+3][m] = a.w;
            float4 w = *(const float4*)&W[(size_t)(n0 + m) * HID + k0 + kq * 4];
            Bs[kq*4+0][m] = w.x; Bs[kq*4+1][m] = w.y;
            Bs[kq*4+2][m] = w.z; Bs[kq*4+3][m] = w.w;
        }
        __syncthreads();
        #pragma unroll
        for (int k = 0; k < 16; k++) {
            float4 a0 = *(const float4*)&As[k][ty * 4];
            float4 a1 = *(const float4*)&As[k][64 + ty * 4];
            float4 w0 = *(const float4*)&Bs[k][tx * 4];
            float4 w1 = *(const float4*)&Bs[k][64 + tx * 4];
            float ar[8] = {a0.x, a0.y, a0.z, a0.w, a1.x, a1.y, a1.z, a1.w};
            float wr[8] = {w0.x, w0.y, w0.z, w0.w, w1.x, w1.y, w1.z, w1.w};
            #pragma unroll
            for (int i = 0; i < 8; i++)
                #pragma unroll
                for (int j = 0; j < 8; j++)
                    acc[i][j] = fmaf(ar[i], wr[j], acc[i][j]);
        }
        __syncthreads();
    }

    #pragma unroll
    for (int i = 0; i < 8; i++) {
        int gm = m0 + (i < 4 ? ty * 4 + i : 64 + ty * 4 + (i - 4));
        if (gm >= R) continue;
        int t = gm >> 6;
        int b = gm & 63;
        #pragma unroll
        for (int j = 0; j < 8; j++) {
            int gn = n0 + (j < 4 ? tx * 4 + j : 64 + tx * 4 + (j - 4));
            float v = acc[i][j] + b1[gn] + b2[gn];
            int g  = gn >> 9;
            int jj = gn & 511;
            Gout[(size_t)((t * 4 + g) * 512 + jj) * 64 + b] = v;
        }
    }
}

// ---------------- one LSTM step (lean; no register staging) ------------------
// Grid 128 x 256 threads. Block owns j0=bid*4..+3 -> 16 gate rows (g*4+jj).
// W slice staged k-major in smem once per step; h chunks (128 k) arrive via
// cp.async into a 2-deep smem ring. GEMM map: s=tid&3 (4-way k-split),
// rq=(tid>>2)&3 (gate), bq=tid>>4 (batch quad). acc[4][4]=16 regs.
// Update map: bb=tid&63, ju=tid>>6. c is in-place global (one owner/elem).
__global__ __launch_bounds__(256) void lstm_step(
    const float* __restrict__ Whh,
    const int*   __restrict__ input_lines,
    int is_enc, int t, int p)
{
    extern __shared__ float sm[];
    float* Wsm = sm;                          // [512][WPITCH]
    float* hs  = sm + 512 * WPITCH;           // [2][128][HPITCH]
    float* gsm = hs + 2 * 128 * HPITCH;       // [16][HPITCH]

    int tid = threadIdx.x;
    int j0  = blockIdx.x * 4;
    int s   = tid & 3;
    int rq  = (tid >> 2) & 3;
    int bq  = tid >> 4;
    int bb  = tid & 63;
    int ju  = tid >> 6;

    const float* __restrict__ hin  = g_Hpp[p];
    float*       __restrict__ hout = g_Hpp[1 - p];
    const float* __restrict__ Gt =
        (is_enc ? g_Ge : g_Gd) + (size_t)t * 4 * HID * BATCH;

    unsigned hs_base = smem_u32(hs);

    // kick off h chunk 0 (k 0..127) via cp.async
    #pragma unroll
    for (int i = 0; i < 8; i++) {
        int sl = tid + i * 256;               // 2048 16B slots
        int k = sl >> 4, q = sl & 15;
        cp_async16(hs_base + (unsigned)(k * HPITCH + q * 4) * 4u,
                   hin + k * 64 + q * 4);
    }
    asm volatile("cp.async.commit_group;");

    // stage W slice k-major (16 rows x 512 k); lr = g*4 + jj
    #pragma unroll
    for (int i = 0; i < 8; i++) {
        int sl = tid + i * 256;
        int lr = sl & 15;
        int kq = sl >> 4;                     // 0..127 (float4 along k)
        int g = lr >> 2, jj = lr & 3;
        float4 w = *(const float4*)&Whh[(size_t)(g * HID + j0 + jj) * HID + kq * 4];
        float* d = &Wsm[(size_t)(kq * 4) * WPITCH + lr];
        d[0 * WPITCH] = w.x; d[1 * WPITCH] = w.y;
        d[2 * WPITCH] = w.z; d[3 * WPITCH] = w.w;
    }

    // update-path early loads (scoreboard-waited at consumption)
    float gpre0 = Gt[(size_t)(0 * HID + j0 + ju) * 64 + bb];
    float gpre1 = Gt[(size_t)(1 * HID + j0 + ju) * 64 + bb];
    float gpre2 = Gt[(size_t)(2 * HID + j0 + ju) * 64 + bb];
    float gpre3 = Gt[(size_t)(3 * HID + j0 + ju) * 64 + bb];
    float hold = hin[(j0 + ju) * 64 + bb];
    float cold = g_Cst[(j0 + ju) * 64 + bb];
    int tok = is_enc ? input_lines[t * 64 + bb] : 1;

    float acc[4][4] = {};

    asm volatile("cp.async.wait_group 0;");
    __syncthreads();

    #pragma unroll
    for (int ch = 0; ch < 4; ch++) {
        int buf = ch & 1;
        if (ch < 3) {
            #pragma unroll
            for (int i = 0; i < 8; i++) {
                int sl = tid + i * 256;
                int k = sl >> 4, q = sl & 15;
                cp_async16(hs_base + (unsigned)(((1 - buf) * 128 + k) * HPITCH + q * 4) * 4u,
                           hin + ((ch + 1) * 128 + k) * 64 + q * 4);
            }
            asm volatile("cp.async.commit_group;");
        }
        #pragma unroll
        for (int kk = 0; kk < 32; kk++) {
            int kl = kk * 4 + s;              // 0..127 within chunk
            float4 w  = *(const float4*)&Wsm[(size_t)(ch * 128 + kl) * WPITCH + rq * 4];
            float4 h4 = *(const float4*)&hs[(size_t)(buf * 128 + kl) * HPITCH + bq * 4];
            float wr[4] = {w.x, w.y, w.z, w.w};
            float hr[4] = {h4.x, h4.y, h4.z, h4.w};
            #pragma unroll
            for (int ri = 0; ri < 4; ri++)
                #pragma unroll
                for (int bi = 0; bi < 4; bi++)
                    acc[ri][bi] = fmaf(wr[ri], hr[bi], acc[ri][bi]);
        }
        if (ch < 3) asm volatile("cp.async.wait_group 0;");
        __syncthreads();
    }

    // reduce over the 4 k-split lanes (lane bits 0..1); each s-lane emits one row
    #pragma unroll
    for (int ri = 0; ri < 4; ri++) {
        #pragma unroll
        for (int bi = 0; bi < 4; bi++) {
            float v = acc[ri][bi];
            v += __shfl_xor_sync(0xffffffffu, v, 1);
            v += __shfl_xor_sync(0xffffffffu, v, 2);
            acc[ri][bi] = v;
        }
        if (s == ri)
            *(float4*)&gsm[(rq * 4 + ri) * HPITCH + bq * 4] =
                make_float4(acc[ri][0], acc[ri][1], acc[ri][2], acc[ri][3]);
    }
    __syncthreads();

    // fused cell update; gate rows g*4 + ju
    {
        float iv = gsm[(0  + ju) * HPITCH + bb] + gpre0;
        float fv = gsm[(4  + ju) * HPITCH + bb] + gpre1;
        float gv = gsm[(8  + ju) * HPITCH + bb] + gpre2;
        float ov = gsm[(12 + ju) * HPITCH + bb] + gpre3;
        float c2 = sigmoidf_(fv) * cold + sigmoidf_(iv) * tanhf(gv);
        float h2 = sigmoidf_(ov) * tanhf(c2);
        if (is_enc && tok == 0) { c2 = cold; h2 = hold; }
        g_Cst[(j0 + ju) * 64 + bb] = c2;
        hout[(j0 + ju) * 64 + bb] = h2;
        if (!is_enc)
            g_Hall[(size_t)(j0 + ju) * NROWS_PAD + t * 64 + bb] = h2;
    }
}

// ---------------- projection + fused log-softmax pieces ---------------------
// A = Hall' [k][m] (k-major), B = W_out rows; 128x128 tile, 8x8 microtile.
__global__ __launch_bounds__(256) void proj_loss_kernel(
    const float* __restrict__ W,
    const float* __restrict__ bout,
    const int*   __restrict__ targets)
{
    __shared__ float As[16][132];
    __shared__ float Bs[16][132];

    int m0 = blockIdx.y * 128;
    int n0 = blockIdx.x * 128;
    int tid = threadIdx.x;
    int tx = tid & 15;
    int ty = tid >> 4;
    float acc[8][8] = {};

    for (int k0 = 0; k0 < HID; k0 += 16) {
        #pragma unroll
        for (int l = 0; l < 2; l++) {
            int idx = tid + l * 256;
            {   // A: Hall'[k][m] already k-major -> direct copy
                int k  = idx >> 5;
                int mq = idx & 31;
                float4 a = *(const float4*)&g_Hall[(size_t)(k0 + k) * NROWS_PAD + m0 + mq * 4];
                *(float4*)&As[k][mq * 4] = a;
            }
            {   // B: gather W rows transposed
                int m  = idx >> 2;
                int kq = idx & 3;
                float4 w = *(const float4*)&W[(size_t)(n0 + m) * HID + k0 + kq * 4];
                Bs[kq*4+0][m] = w.x; Bs[kq*4+1][m] = w.y;
                Bs[kq*4+2][m] = w.z; Bs[kq*4+3][m] = w.w;
            }
        }
        __syncthreads();
        #pragma unroll
        for (int k = 0; k < 16; k++) {
            float4 a0 = *(const float4*)&As[k][ty * 4];
            float4 a1 = *(const float4*)&As[k][64 + ty * 4];
            float4 w0 = *(const float4*)&Bs[k][tx * 4];
            float4 w1 = *(const float4*)&Bs[k][64 + tx * 4];
            float ar[8] = {a0.x, a0.y, a0.z, a0.w, a1.x, a1.y, a1.z, a1.w};
            float wr[8] = {w0.x, w0.y, w0.z, w0.w, w1.x, w1.y, w1.z, w1.w};
            #pragma unroll
            for (int i = 0; i < 8; i++)
                #pragma unroll
                for (int j = 0; j < 8; j++)
                    acc[i][j] = fmaf(ar[i], wr[j], acc[i][j]);
        }
        __syncthreads();
    }

    int   gncol[8];
    float bj[8];
    #pragma unroll
    for (int j = 0; j < 8; j++) {
        gncol[j] = n0 + (j < 4 ? tx * 4 + j : 64 + tx * 4 + (j - 4));
        bj[j] = bout[gncol[j]];
    }
    #pragma unroll
    for (int i = 0; i < 8; i++) {
        int gm = m0 + (i < 4 ? ty * 4 + i : 64 + ty * 4 + (i - 4));
        bool valid = (gm < NROWS);
        int tgt = valid ? targets[gm + BATCH] : -1;
        float sum = 0.0f;
        #pragma unroll
        for (int j = 0; j < 8; j++) {
            float logit = acc[i][j] + bj[j];
            sum += __expf(logit);
            if (valid && gncol[j] == tgt) g_rowtgt[gm] = logit;
        }
        #pragma unroll
        for (int o = 8; o > 0; o >>= 1)
            sum += __shfl_xor_sync(0xffffffffu, sum, o, 16);
        if (valid && tx == 0) atomicAdd(&g_rowsum[gm], sum);
    }
}

// ---------------- final loss reduction ---------------------------------------
__global__ void loss_reduce_kernel(float* __restrict__ out)
{
    __shared__ float sbuf[256];
    int tid = threadIdx.x;
    float s = 0.0f;
    for (int r = tid; r < NROWS; r += 256)
        s += logf(g_rowsum[r]) - g_rowtgt[r];
    sbuf[tid] = s;
    __syncthreads();
    for (int o = 128; o > 0; o >>= 1) {
        if (tid < o) sbuf[tid] += sbuf[tid + o];
        __syncthreads();
    }
    if (tid == 0) out[0] = sbuf[0] / (float)BATCH;
}

// ---------------- launch -----------------------------------------------------
extern "C" void kernel_launch(void* const* d_in, const int* in_sizes, int n_in,
                              void* d_out, int out_size)
{
    (void)in_sizes; (void)n_in; (void)out_size;
    const int*   input_lines  = (const int*)  d_in[0];
    const int*   target_lines = (const int*)  d_in[1];
    const float* emb_in       = (const float*)d_in[2];
    const float* emb_tgt      = (const float*)d_in[3];
    const float* W_ih_e       = (const float*)d_in[4];
    const float* W_hh_e       = (const float*)d_in[5];
    const float* b_ih_e       = (const float*)d_in[6];
    const float* b_hh_e       = (const float*)d_in[7];
    const float* W_ih_d       = (const float*)d_in[8];
    const float* W_hh_d       = (const float*)d_in[9];
    const float* b_ih_d       = (const float*)d_in[10];
    const float* b_hh_d       = (const float*)d_in[11];
    const float* W_out        = (const float*)d_in[12];
    const float* b_out        = (const float*)d_in[13];
    float* out = (float*)d_out;

    const int SMEM_BYTES = (512 * WPITCH + 2 * 128 * HPITCH + 16 * HPITCH) * 4;
    cudaFuncSetAttribute(lstm_step,
                         cudaFuncAttributeMaxDynamicSharedMemorySize,
                         SMEM_BYTES);

    init_kernel<<<(HID * BATCH + 255) / 256, 256>>>();

    embed_gemm128<<<dim3(G4 / 128, 24), 256>>>(
        input_lines, emb_in, W_ih_e, b_ih_e, b_hh_e, 1, SRC_LEN * BATCH);
    embed_gemm128<<<dim3(G4 / 128, 24), 256>>>(
        target_lines, emb_tgt, W_ih_d, b_ih_d, b_hh_d, 0, DSTEPS * BATCH);

    int p = 0;
    for (int t = 0; t < SRC_LEN; t++) {
        lstm_step<<<HID / 4, 256, SMEM_BYTES>>>(W_hh_e, input_lines, 1, t, p);
        p ^= 1;
    }
    for (int t = 0; t < DSTEPS; t++) {
        lstm_step<<<HID / 4, 256, SMEM_BYTES>>>(W_hh_d, input_lines, 0, t, p);
        p ^= 1;
    }

    proj_loss_kernel<<<dim3(VOCAB / 128, NROWS_PAD / 128), 256>>>(
        W_out, b_out, target_lines);

    loss_reduce_kernel<<<1, 256>>>(out);
}